// round 11
// baseline (speedup 1.0000x reference)
#include <cuda_runtime.h>
#include <math.h>

#define BB 32
#define LL 196
#define DD 512
#define HH 512
#define EE 256
#define TT 128
#define VV 512
#define A1 256
#define A2 128
#define GG 2048            // 4*H
#define NH 358
#define HZE (HH + DD + EE) // 1280
#define NPG (A1 + GG)      // 2304
#define PADTOK 0
#define NBLK 296
#define NTHR 256
#define XP 18              // x1t row pad (even -> float2 aligned, stride 18 -> 2-way max conflict)

// ---------------- scratch (no allocation allowed) ----------------
__device__ float g_eseq[BB * TT * EE];
__device__ float g_prea[BB * LL * A1];
__device__ float g_egate[BB * TT * GG];
__device__ float g_h[BB * HH];
__device__ float g_c[BB * HH];
__device__ float g_hpg[BB * NPG];
__device__ float g_scores[BB * LL];
__device__ float g_z[BB * DD];
__device__ float g_hze[BB * TT * HZE];
__device__ float g_x1[BB * TT * NH];
__device__ float g_x2[BB * TT * NH];

// ---------------- software grid barrier (generation counter) ----------------
__device__ unsigned g_bar_count;
__device__ volatile unsigned g_bar_gen;

__device__ __forceinline__ void grid_sync() {
    __syncthreads();
    if (threadIdx.x == 0) {
        unsigned gen = g_bar_gen;
        __threadfence();
        if (atomicAdd(&g_bar_count, 1u) == NBLK - 1) {
            g_bar_count = 0;
            __threadfence();
            g_bar_gen = gen + 1;
        } else {
            while (g_bar_gen == gen) {}
        }
        __threadfence();
    }
    __syncthreads();
}

__device__ __forceinline__ float tanh_fast(float x) {
    float y;
    asm("tanh.approx.f32 %0, %1;" : "=f"(y) : "f"(x));
    return y;
}

// ---------------- embedding gather (shift-right w/ pad) ----------------
__global__ void k_embed(const int* __restrict__ y, const float* __restrict__ embed) {
    int bt = blockIdx.x;
    int b = bt / TT, t = bt % TT;
    int tok = (t == 0) ? PADTOK : y[b * TT + (t - 1)];
    float v = embed[tok * EE + threadIdx.x];
    g_eseq[bt * EE + threadIdx.x] = v;
    g_hze[bt * HZE + HH + DD + threadIdx.x] = v;
}

// ---------------- generic tiled SGEMM: C = act(A*W + bias) ----------------
template <int ACT>
__global__ void k_sgemm(const float* __restrict__ A, int lda,
                        const float* __restrict__ W, int ldw,
                        const float* __restrict__ bias,
                        float* __restrict__ C, int ldc,
                        int M, int N, int K) {
    __shared__ float As[16][65];
    __shared__ float Ws[16][65];
    int tx = threadIdx.x % 16, ty = threadIdx.x / 16;
    int row0 = blockIdx.y * 64;
    int col0 = blockIdx.x * 64;
    float acc[4][4] = {};
    for (int k0 = 0; k0 < K; k0 += 16) {
        for (int i = threadIdx.x; i < 64 * 16; i += 256) {
            int r = i >> 4, kk = i & 15;
            int gr = row0 + r, gk = k0 + kk;
            As[kk][r] = (gr < M && gk < K) ? A[gr * lda + gk] : 0.f;
        }
        for (int i = threadIdx.x; i < 16 * 64; i += 256) {
            int kk = i >> 6, c = i & 63;
            int gk = k0 + kk, gc = col0 + c;
            Ws[kk][c] = (gk < K && gc < N) ? W[gk * ldw + gc] : 0.f;
        }
        __syncthreads();
#pragma unroll
        for (int kk = 0; kk < 16; kk++) {
            float a_[4], w_[4];
#pragma unroll
            for (int i = 0; i < 4; i++) a_[i] = As[kk][ty * 4 + i];
#pragma unroll
            for (int j = 0; j < 4; j++) w_[j] = Ws[kk][tx * 4 + j];
#pragma unroll
            for (int i = 0; i < 4; i++)
#pragma unroll
                for (int j = 0; j < 4; j++) acc[i][j] += a_[i] * w_[j];
        }
        __syncthreads();
    }
#pragma unroll
    for (int i = 0; i < 4; i++) {
        int r = row0 + ty * 4 + i;
        if (r >= M) continue;
#pragma unroll
        for (int j = 0; j < 4; j++) {
            int c = col0 + tx * 4 + j;
            if (c >= N) continue;
            float v = acc[i][j] + (bias ? bias[c] : 0.f);
            if (ACT == 1) v = tanhf(v);
            C[r * ldc + c] = v;
        }
    }
}

// ---------------- persistent step-loop kernel ----------------
struct SmemA1 { float h1[HH]; };
struct SmemBB { __align__(16) float x1t[A1][XP]; float red[16][4]; };   // ~18.3 KB
struct SmemA2 { float h4[4][HH]; };                                     // 8 KB
struct SmemC  { float al[LL]; float red[8]; float cpart[2][128]; };
struct SmemD  { float zs[4][DD]; float gacc[4][4][16]; };               // 9.2 KB
union StepSmem { SmemA1 a1; SmemBB b; SmemA2 a2; SmemC c; SmemD d; };

__global__ __launch_bounds__(NTHR, 2)
void k_steps(const float* __restrict__ a_feat,
             const float* __restrict__ h0, const float* __restrict__ c0,
             const float* __restrict__ w1h,   // att_w1 + D*A1 (ld A1)
             const float* __restrict__ whh,   // ld GG
             const float* __restrict__ bhh,
             const float* __restrict__ w2, const float* __restrict__ b2,
             const float* __restrict__ w3, const float* __restrict__ b3,
             const float* __restrict__ wih) {
    __shared__ StepSmem sm;
    int bid = blockIdx.x;
    int tid = threadIdx.x;

    for (int i = bid * NTHR + tid; i < BB * HH; i += NBLK * NTHR) {
        g_h[i] = h0[i];
        g_c[i] = c0[i];
    }
    grid_sync();

    for (int t = 0; t < TT; t++) {
        // ======== P1: A1 only — hpg[b, 0:256] = h[b] @ w1h  (32 units) ========
        if (bid < 32) {
            int b = bid;
            for (int i = tid; i < HH; i += NTHR) sm.a1.h1[i] = g_h[b * HH + i];
            __syncthreads();
            float acc = 0.f;
#pragma unroll 16
            for (int k = 0; k < HH; k++)
                acc += sm.a1.h1[k] * w1h[k * A1 + tid];
            g_hpg[b * NPG + tid] = acc;
        }
        grid_sync();

        // ======== P2: attention B (448 units) + A2 lstm-hh proj (128 units) ====
        for (int u = bid; u < 576; u += NBLK) {
            __syncthreads();     // protect smem reuse across units
            if (u < 448) {
                // B unit: 16 rows x 128 cols. b = u/14, tile = u%14
                int b = u / 14;
                int l0 = (u % 14) * 16;
                // stage transposed tanh(x1): x1t[k][r]
                float hpk = g_hpg[b * NPG + tid];     // k = tid (A1 == NTHR)
#pragma unroll
                for (int i = 0; i < 16; i++) {
                    int l = l0 + i;
                    float v = 0.f;
                    if (l < LL) v = tanh_fast(g_prea[(b * LL + l) * A1 + tid] + hpk);
                    sm.b.x1t[tid][i] = v;
                }
                __syncthreads();
                int lane = tid & 31, w = tid >> 5;     // 8 warps
                int rh = w & 1, ch = w >> 1;           // row-half(8), col-quarter(32)
                int rg = lane >> 3, cq = lane & 7;
                int r0 = rh * 8 + rg * 2;              // 2 rows per lane
                int c0 = ch * 32 + cq * 4;             // 4 cols per lane
                float acc[2][4] = {};
                const float* w2p = w2 + c0;
#pragma unroll 8
                for (int k = 0; k < A1; k++) {
                    float2 av = *reinterpret_cast<const float2*>(&sm.b.x1t[k][r0]);
                    float4 wv = *reinterpret_cast<const float4*>(&w2p[k * A2]);
                    acc[0][0] += av.x * wv.x; acc[0][1] += av.x * wv.y;
                    acc[0][2] += av.x * wv.z; acc[0][3] += av.x * wv.w;
                    acc[1][0] += av.y * wv.x; acc[1][1] += av.y * wv.y;
                    acc[1][2] += av.y * wv.z; acc[1][3] += av.y * wv.w;
                }
                float b2v0 = b2[c0], b2v1 = b2[c0 + 1], b2v2 = b2[c0 + 2], b2v3 = b2[c0 + 3];
                float w3v0 = w3[c0], w3v1 = w3[c0 + 1], w3v2 = w3[c0 + 2], w3v3 = w3[c0 + 3];
#pragma unroll
                for (int i = 0; i < 2; i++) {
                    float p = tanh_fast(acc[i][0] + b2v0) * w3v0
                            + tanh_fast(acc[i][1] + b2v1) * w3v1
                            + tanh_fast(acc[i][2] + b2v2) * w3v2
                            + tanh_fast(acc[i][3] + b2v3) * w3v3;
                    p += __shfl_down_sync(0xffffffffu, p, 4, 8);
                    p += __shfl_down_sync(0xffffffffu, p, 2, 8);
                    p += __shfl_down_sync(0xffffffffu, p, 1, 8);
                    if (cq == 0) sm.b.red[r0 + i][ch] = p;
                }
                __syncthreads();
                if (tid < 16) {
                    int l = l0 + tid;
                    if (l < LL) {
                        float s = sm.b.red[tid][0] + sm.b.red[tid][1]
                                + sm.b.red[tid][2] + sm.b.red[tid][3] + b3[0];
                        g_scores[b * LL + l] = s;
                    }
                }
            } else {
                // A2 unit: hpg[b, 256:2304] = h@whh + bhh.
                // unit = (cch 0..15: 128 cols, bg 0..7: 4 batches)
                int a2u = u - 448;
                int cch = a2u >> 3;
                int bg = a2u & 7;
                for (int i = tid; i < 4 * HH; i += NTHR) {
                    int bi = i >> 9, kk = i & 511;
                    sm.a2.h4[bi][kk] = g_h[(bg * 4 + bi) * HH + kk];
                }
                __syncthreads();
                int c = cch * 128 + (tid & 127);      // 0..2047
                int b0 = (tid >> 7) * 2;              // batches b0, b0+1 of group
                float bias = bhh[c];
                float acc0 = bias, acc1 = bias;
                const float* hr0 = sm.a2.h4[b0];
                const float* hr1 = sm.a2.h4[b0 + 1];
#pragma unroll 16
                for (int k = 0; k < HH; k++) {
                    float wv = whh[(size_t)k * GG + c];
                    acc0 += hr0[k] * wv;
                    acc1 += hr1[k] * wv;
                }
                g_hpg[(bg * 4 + b0) * NPG + A1 + c] = acc0;
                g_hpg[(bg * 4 + b0 + 1) * NPG + A1 + c] = acc1;
            }
        }
        grid_sync();

        // ======== P3: softmax + z (128 units = 32 b x 4 d-chunks(128)) ========
        if (bid < 128) {
            int b = bid >> 2;
            int dch = bid & 3;
            int lane = tid & 31, warp = tid >> 5;
            float v = (tid < LL) ? g_scores[b * LL + tid] : -1e30f;
            float m = v;
#pragma unroll
            for (int off = 16; off; off >>= 1) m = fmaxf(m, __shfl_xor_sync(0xffffffffu, m, off));
            if (lane == 0) sm.c.red[warp] = m;
            __syncthreads();
            m = sm.c.red[0];
#pragma unroll
            for (int i = 1; i < 8; i++) m = fmaxf(m, sm.c.red[i]);
            float e = (tid < LL) ? expf(v - m) : 0.f;
            __syncthreads();
            float sum = e;
#pragma unroll
            for (int off = 16; off; off >>= 1) sum += __shfl_xor_sync(0xffffffffu, sum, off);
            if (lane == 0) sm.c.red[warp] = sum;
            __syncthreads();
            sum = sm.c.red[0] + sm.c.red[1] + sm.c.red[2] + sm.c.red[3]
                + sm.c.red[4] + sm.c.red[5] + sm.c.red[6] + sm.c.red[7];
            float inv = 1.f / sum;
            if (tid < LL) sm.c.al[tid] = e * inv;
            __syncthreads();
            int dl = tid & 127;
            int lh = tid >> 7;
            int d = dch * 128 + dl;
            const float* ab = a_feat + (size_t)(b * LL + lh * 98) * DD + d;
            const float* alv = &sm.c.al[lh * 98];
            float acc = 0.f;
#pragma unroll 14
            for (int l = 0; l < 98; l++) acc += alv[l] * ab[(size_t)l * DD];
            sm.c.cpart[lh][dl] = acc;
            __syncthreads();
            if (tid < 128) {
                float zv = sm.c.cpart[0][tid] + sm.c.cpart[1][tid];
                int dg = dch * 128 + tid;
                g_z[b * DD + dg] = zv;
                g_hze[(size_t)(b * TT + t) * HZE + HH + dg] = zv;
            }
        }
        grid_sync();

        // ======== P4: LSTM (256 units = 32 jp-chunks(16) x 8 bg(4)) ===========
        if (bid < 256) {
            int jpch = bid >> 3;
            int bg = bid & 7;
            for (int i = tid; i < 4 * DD; i += NTHR) {
                int bi = i >> 9, kk = i & 511;
                sm.d.zs[bi][kk] = g_z[(bg * 4 + bi) * DD + kk];
            }
            __syncthreads();
            int jl = tid & 15;
            int gate = (tid >> 4) & 3;
            int bi = tid >> 6;
            int jp = jpch * 16 + jl;
            const float* Wg = wih + (size_t)gate * HH + jp;
            const float* zrow = sm.d.zs[bi];
            float acc = 0.f;
#pragma unroll 32
            for (int d = 0; d < DD; d++)
                acc += zrow[d] * Wg[(size_t)d * GG];
            sm.d.gacc[gate][bi][jl] = acc;
            __syncthreads();
            if (tid < 64) {
                int jl2 = tid & 15;
                int bi2 = tid >> 4;
                int b = bg * 4 + bi2;
                int jp2 = jpch * 16 + jl2;
                const float* eg = g_egate + (size_t)(b * TT + t) * GG;
                const float* hg = g_hpg + b * NPG + A1;
                float ai = sm.d.gacc[0][bi2][jl2] + eg[jp2]        + hg[jp2];
                float af = sm.d.gacc[1][bi2][jl2] + eg[jp2 + 512]  + hg[jp2 + 512];
                float ag = sm.d.gacc[2][bi2][jl2] + eg[jp2 + 1024] + hg[jp2 + 1024];
                float ao = sm.d.gacc[3][bi2][jl2] + eg[jp2 + 1536] + hg[jp2 + 1536];
                float i_ = 1.f / (1.f + expf(-ai));
                float f_ = 1.f / (1.f + expf(-af));
                float o_ = 1.f / (1.f + expf(-ao));
                float gv = tanhf(ag);
                float c = f_ * g_c[b * HH + jp2] + i_ * gv;
                float h = o_ * tanhf(c);
                g_c[b * HH + jp2] = c;
                g_h[b * HH + jp2] = h;
                g_hze[(size_t)(b * TT + t) * HZE + jp2] = h;
            }
        }
        grid_sync();
    }
}

// ---------------- launch ----------------
extern "C" void kernel_launch(void* const* d_in, const int* in_sizes, int n_in,
                              void* d_out, int out_size) {
    const float* a      = (const float*)d_in[0];
    const float* h0     = (const float*)d_in[1];
    const float* c0     = (const float*)d_in[2];
    const int*   y      = (const int*)d_in[3];
    const float* att_w1 = (const float*)d_in[4];
    const float* att_b1 = (const float*)d_in[5];
    const float* att_w2 = (const float*)d_in[6];
    const float* att_b2 = (const float*)d_in[7];
    const float* att_w3 = (const float*)d_in[8];
    const float* att_b3 = (const float*)d_in[9];
    const float* w_ih   = (const float*)d_in[10];
    const float* w_hh   = (const float*)d_in[11];
    const float* b_ih   = (const float*)d_in[12];
    const float* b_hh   = (const float*)d_in[13];
    const float* embed  = (const float*)d_in[14];
    const float* out_w1 = (const float*)d_in[15];
    const float* out_b1 = (const float*)d_in[16];
    const float* out_w2 = (const float*)d_in[17];
    const float* out_b2 = (const float*)d_in[18];
    const float* out_w3 = (const float*)d_in[19];
    const float* out_b3 = (const float*)d_in[20];
    float* out = (float*)d_out;

    float *prea, *eseq, *egate, *hze, *x1, *x2;
    cudaGetSymbolAddress((void**)&prea,  g_prea);
    cudaGetSymbolAddress((void**)&eseq,  g_eseq);
    cudaGetSymbolAddress((void**)&egate, g_egate);
    cudaGetSymbolAddress((void**)&hze,   g_hze);
    cudaGetSymbolAddress((void**)&x1,    g_x1);
    cudaGetSymbolAddress((void**)&x2,    g_x2);

    k_embed<<<BB * TT, EE>>>(y, embed);

    k_sgemm<0><<<dim3((A1 + 63) / 64, (BB * LL + 63) / 64), 256>>>(
        a, DD, att_w1, A1, att_b1, prea, A1, BB * LL, A1, DD);
    k_sgemm<0><<<dim3((GG + 63) / 64, (BB * TT + 63) / 64), 256>>>(
        eseq, EE, w_ih + (size_t)DD * GG, GG, b_ih, egate, GG, BB * TT, GG, EE);

    k_steps<<<NBLK, NTHR>>>(a, h0, c0,
                            att_w1 + (size_t)DD * A1, w_hh, b_hh,
                            att_w2, att_b2, att_w3, att_b3, w_ih);

    k_sgemm<1><<<dim3((NH + 63) / 64, (BB * TT + 63) / 64), 256>>>(
        hze, HZE, out_w1, NH, out_b1, x1, NH, BB * TT, NH, HZE);
    k_sgemm<1><<<dim3((NH + 63) / 64, (BB * TT + 63) / 64), 256>>>(
        x1, NH, out_w2, NH, out_b2, x2, NH, BB * TT, NH, NH);
    k_sgemm<0><<<dim3((VV + 63) / 64, (BB * TT + 63) / 64), 256>>>(
        x2, NH, out_w3, VV, out_b3, out, VV, BB * TT, VV, NH);
}

// round 12
// speedup vs baseline: 1.0363x; 1.0363x over previous
#include <cuda_runtime.h>
#include <math.h>

#define BB 32
#define LL 196
#define DD 512
#define HH 512
#define EE 256
#define TT 128
#define VV 512
#define A1 256
#define A2 128
#define GG 2048            // 4*H
#define NH 358
#define HZE (HH + DD + EE) // 1280
#define NPG (A1 + GG)      // 2304
#define PADTOK 0
#define NBLK 296
#define NTHR 256
#define NGRP 37            // 296 / 8
#define XP 18              // x1t row pad

// ---------------- scratch (no allocation allowed) ----------------
__device__ float g_eseq[BB * TT * EE];
__device__ float g_prea[BB * LL * A1];
__device__ float g_egate[BB * TT * GG];
__device__ float g_h[BB * HH];
__device__ float g_c[BB * HH];
__device__ float g_hpg[BB * NPG];
__device__ float g_scores[BB * LL];
__device__ float g_z[BB * DD];
__device__ float g_hze[BB * TT * HZE];
__device__ float g_x1[BB * TT * NH];
__device__ float g_x2[BB * TT * NH];

// ---------------- hierarchical grid barrier (generation-tagged) ----------------
// Counters never reset; equality comparisons hold under mod-2^32 arithmetic.
__device__ unsigned g_cnt0[NGRP];
__device__ unsigned g_cnt1;
__device__ volatile unsigned g_bar_gen;

__device__ __forceinline__ void grid_sync() {
    __syncthreads();
    if (threadIdx.x == 0) {
        unsigned gen = g_bar_gen;
        __threadfence();
        unsigned grp = (unsigned)blockIdx.x >> 3;
        unsigned old = atomicAdd(&g_cnt0[grp], 1u);
        bool done = false;
        if (old == 8u * gen + 7u) {                 // last of this group, this gen
            unsigned o1 = atomicAdd(&g_cnt1, 1u);
            if (o1 == (unsigned)NGRP * gen + (NGRP - 1u)) {  // last group
                __threadfence();
                g_bar_gen = gen + 1u;
                done = true;
            }
        }
        if (!done) while (g_bar_gen == gen) {}
        __threadfence();
    }
    __syncthreads();
}

__device__ __forceinline__ float tanh_fast(float x) {
    float y;
    asm("tanh.approx.f32 %0, %1;" : "=f"(y) : "f"(x));
    return y;
}

// ---------------- embedding gather (shift-right w/ pad) ----------------
__global__ void k_embed(const int* __restrict__ y, const float* __restrict__ embed) {
    int bt = blockIdx.x;
    int b = bt / TT, t = bt % TT;
    int tok = (t == 0) ? PADTOK : y[b * TT + (t - 1)];
    float v = embed[tok * EE + threadIdx.x];
    g_eseq[bt * EE + threadIdx.x] = v;
    g_hze[bt * HZE + HH + DD + threadIdx.x] = v;
}

// ---------------- generic tiled SGEMM: C = act(A*W + bias) ----------------
template <int ACT>
__global__ void k_sgemm(const float* __restrict__ A, int lda,
                        const float* __restrict__ W, int ldw,
                        const float* __restrict__ bias,
                        float* __restrict__ C, int ldc,
                        int M, int N, int K) {
    __shared__ float As[16][65];
    __shared__ float Ws[16][65];
    int tx = threadIdx.x % 16, ty = threadIdx.x / 16;
    int row0 = blockIdx.y * 64;
    int col0 = blockIdx.x * 64;
    float acc[4][4] = {};
    for (int k0 = 0; k0 < K; k0 += 16) {
        for (int i = threadIdx.x; i < 64 * 16; i += 256) {
            int r = i >> 4, kk = i & 15;
            int gr = row0 + r, gk = k0 + kk;
            As[kk][r] = (gr < M && gk < K) ? A[gr * lda + gk] : 0.f;
        }
        for (int i = threadIdx.x; i < 16 * 64; i += 256) {
            int kk = i >> 6, c = i & 63;
            int gk = k0 + kk, gc = col0 + c;
            Ws[kk][c] = (gk < K && gc < N) ? W[gk * ldw + gc] : 0.f;
        }
        __syncthreads();
#pragma unroll
        for (int kk = 0; kk < 16; kk++) {
            float a_[4], w_[4];
#pragma unroll
            for (int i = 0; i < 4; i++) a_[i] = As[kk][ty * 4 + i];
#pragma unroll
            for (int j = 0; j < 4; j++) w_[j] = Ws[kk][tx * 4 + j];
#pragma unroll
            for (int i = 0; i < 4; i++)
#pragma unroll
                for (int j = 0; j < 4; j++) acc[i][j] += a_[i] * w_[j];
        }
        __syncthreads();
    }
#pragma unroll
    for (int i = 0; i < 4; i++) {
        int r = row0 + ty * 4 + i;
        if (r >= M) continue;
#pragma unroll
        for (int j = 0; j < 4; j++) {
            int c = col0 + tx * 4 + j;
            if (c >= N) continue;
            float v = acc[i][j] + (bias ? bias[c] : 0.f);
            if (ACT == 1) v = tanhf(v);
            C[r * ldc + c] = v;
        }
    }
}

// ---------------- persistent step-loop kernel ----------------
struct SmemA1 { float h1[HH]; };
struct SmemA2 { float h4[4][HH]; };                                     // 8 KB
struct SmemBB { __align__(16) float x1t[A1][XP]; float red[16][4]; };   // ~18.3 KB
struct SmemC  { float al[LL]; float red[8]; float cpart[2][128]; };
struct SmemD  { float zs[4][DD]; float gacc[4][4][16]; };               // 9.2 KB
union StepSmem { SmemA1 a1; SmemA2 a2; SmemBB b; SmemC c; SmemD d; };

__global__ __launch_bounds__(NTHR, 2)
void k_steps(const float* __restrict__ a_feat,
             const float* __restrict__ h0, const float* __restrict__ c0,
             const float* __restrict__ w1h,   // att_w1 + D*A1 (ld A1)
             const float* __restrict__ whh,   // ld GG
             const float* __restrict__ bhh,
             const float* __restrict__ w2, const float* __restrict__ b2,
             const float* __restrict__ w3, const float* __restrict__ b3,
             const float* __restrict__ wih) {
    __shared__ StepSmem sm;
    int bid = blockIdx.x;
    int tid = threadIdx.x;

    for (int i = bid * NTHR + tid; i < BB * HH; i += NBLK * NTHR) {
        g_h[i] = h0[i];
        g_c[i] = c0[i];
    }
    grid_sync();

    for (int t = 0; t < TT; t++) {
        // ======== P1: A1 (32 units) + A2 (256 units: 64 cols x 4 b) ========
        if (bid < 32) {
            int b = bid;
            for (int i = tid; i < HH; i += NTHR) sm.a1.h1[i] = g_h[b * HH + i];
            __syncthreads();
            float acc = 0.f;
#pragma unroll 16
            for (int k = 0; k < HH; k++)
                acc += sm.a1.h1[k] * __ldcg(&w1h[k * A1 + tid]);
            g_hpg[b * NPG + tid] = acc;
        } else if (bid < 288) {
            int a2u = bid - 32;
            int cch = a2u >> 3;               // 0..31 (64-col chunk)
            int bg = a2u & 7;                 // 0..7 (4 batches)
            for (int i = tid; i < 4 * HH; i += NTHR) {
                int bi = i >> 9, kk = i & 511;
                sm.a2.h4[bi][kk] = g_h[(bg * 4 + bi) * HH + kk];
            }
            __syncthreads();
            int col = cch * 64 + (tid & 63);  // 0..2047
            int bi = tid >> 6;                // 0..3
            const float* hrow = sm.a2.h4[bi];
            float acc = bhh[col];
#pragma unroll 32
            for (int k = 0; k < HH; k++)
                acc += hrow[k] * __ldcg(&whh[(size_t)k * GG + col]);
            g_hpg[(bg * 4 + bi) * NPG + A1 + col] = acc;
        }
        grid_sync();

        // ======== P2: attention B (416 units = 32 b x 13 l-tiles(16)) ========
        for (int u = bid; u < 416; u += NBLK) {
            __syncthreads();     // protect smem reuse across units
            int b = u / 13;
            int l0 = (u % 13) * 16;
            float hpk = g_hpg[b * NPG + tid];     // k = tid (A1 == NTHR)
#pragma unroll
            for (int i = 0; i < 16; i++) {
                int l = l0 + i;
                float v = 0.f;
                if (l < LL) v = tanh_fast(__ldcg(&g_prea[(b * LL + l) * A1 + tid]) + hpk);
                sm.b.x1t[tid][i] = v;
            }
            __syncthreads();
            int lane = tid & 31, w = tid >> 5;     // 8 warps
            int rh = w & 1, ch = w >> 1;           // row-half(8), col-quarter(32)
            int rg = lane >> 3, cq = lane & 7;
            int r0 = rh * 8 + rg * 2;              // 2 rows per lane
            int c0 = ch * 32 + cq * 4;             // 4 cols per lane
            float acc[2][4] = {};
            const float* w2p = w2 + c0;            // w2 stays L1-resident (.ca)
#pragma unroll 8
            for (int k = 0; k < A1; k++) {
                float2 av = *reinterpret_cast<const float2*>(&sm.b.x1t[k][r0]);
                float4 wv = *reinterpret_cast<const float4*>(&w2p[k * A2]);
                acc[0][0] += av.x * wv.x; acc[0][1] += av.x * wv.y;
                acc[0][2] += av.x * wv.z; acc[0][3] += av.x * wv.w;
                acc[1][0] += av.y * wv.x; acc[1][1] += av.y * wv.y;
                acc[1][2] += av.y * wv.z; acc[1][3] += av.y * wv.w;
            }
            float b2v0 = b2[c0], b2v1 = b2[c0 + 1], b2v2 = b2[c0 + 2], b2v3 = b2[c0 + 3];
            float w3v0 = w3[c0], w3v1 = w3[c0 + 1], w3v2 = w3[c0 + 2], w3v3 = w3[c0 + 3];
#pragma unroll
            for (int i = 0; i < 2; i++) {
                float p = tanh_fast(acc[i][0] + b2v0) * w3v0
                        + tanh_fast(acc[i][1] + b2v1) * w3v1
                        + tanh_fast(acc[i][2] + b2v2) * w3v2
                        + tanh_fast(acc[i][3] + b2v3) * w3v3;
                p += __shfl_down_sync(0xffffffffu, p, 4, 8);
                p += __shfl_down_sync(0xffffffffu, p, 2, 8);
                p += __shfl_down_sync(0xffffffffu, p, 1, 8);
                if (cq == 0) sm.b.red[r0 + i][ch] = p;
            }
            __syncthreads();
            if (tid < 16) {
                int l = l0 + tid;
                if (l < LL) {
                    float s = sm.b.red[tid][0] + sm.b.red[tid][1]
                            + sm.b.red[tid][2] + sm.b.red[tid][3] + b3[0];
                    g_scores[b * LL + l] = s;
                }
            }
        }
        grid_sync();

        // ======== P3: softmax + z (128 units = 32 b x 4 d-chunks(128)) ========
        if (bid < 128) {
            int b = bid >> 2;
            int dch = bid & 3;
            int lane = tid & 31, warp = tid >> 5;
            float v = (tid < LL) ? g_scores[b * LL + tid] : -1e30f;
            float m = v;
#pragma unroll
            for (int off = 16; off; off >>= 1) m = fmaxf(m, __shfl_xor_sync(0xffffffffu, m, off));
            if (lane == 0) sm.c.red[warp] = m;
            __syncthreads();
            m = sm.c.red[0];
#pragma unroll
            for (int i = 1; i < 8; i++) m = fmaxf(m, sm.c.red[i]);
            float e = (tid < LL) ? expf(v - m) : 0.f;
            __syncthreads();
            float sum = e;
#pragma unroll
            for (int off = 16; off; off >>= 1) sum += __shfl_xor_sync(0xffffffffu, sum, off);
            if (lane == 0) sm.c.red[warp] = sum;
            __syncthreads();
            sum = sm.c.red[0] + sm.c.red[1] + sm.c.red[2] + sm.c.red[3]
                + sm.c.red[4] + sm.c.red[5] + sm.c.red[6] + sm.c.red[7];
            float inv = 1.f / sum;
            if (tid < LL) sm.c.al[tid] = e * inv;
            __syncthreads();
            int dl = tid & 127;
            int lh = tid >> 7;
            int d = dch * 128 + dl;
            const float* ab = a_feat + (size_t)(b * LL + lh * 98) * DD + d;
            const float* alv = &sm.c.al[lh * 98];
            float acc = 0.f;
#pragma unroll 14
            for (int l = 0; l < 98; l++) acc += alv[l] * __ldcg(&ab[(size_t)l * DD]);
            sm.c.cpart[lh][dl] = acc;
            __syncthreads();
            if (tid < 128) {
                float zv = sm.c.cpart[0][tid] + sm.c.cpart[1][tid];
                int dg = dch * 128 + tid;
                g_z[b * DD + dg] = zv;
                g_hze[(size_t)(b * TT + t) * HZE + HH + dg] = zv;
            }
        }
        grid_sync();

        // ======== P4: LSTM (256 units = 32 jp-chunks(16) x 8 bg(4)) ===========
        if (bid < 256) {
            int jpch = bid >> 3;
            int bg = bid & 7;
            for (int i = tid; i < 4 * DD; i += NTHR) {
                int bi = i >> 9, kk = i & 511;
                sm.d.zs[bi][kk] = g_z[(bg * 4 + bi) * DD + kk];
            }
            __syncthreads();
            int jl = tid & 15;
            int gate = (tid >> 4) & 3;
            int bi = tid >> 6;
            int jp = jpch * 16 + jl;
            const float* Wg = wih + (size_t)gate * HH + jp;
            const float* zrow = sm.d.zs[bi];
            float acc = 0.f;
#pragma unroll 32
            for (int d = 0; d < DD; d++)
                acc += zrow[d] * __ldcg(&Wg[(size_t)d * GG]);
            sm.d.gacc[gate][bi][jl] = acc;
            __syncthreads();
            if (tid < 64) {
                int jl2 = tid & 15;
                int bi2 = tid >> 4;
                int b = bg * 4 + bi2;
                int jp2 = jpch * 16 + jl2;
                const float* eg = g_egate + (size_t)(b * TT + t) * GG;
                const float* hg = g_hpg + b * NPG + A1;
                float ai = sm.d.gacc[0][bi2][jl2] + eg[jp2]        + hg[jp2];
                float af = sm.d.gacc[1][bi2][jl2] + eg[jp2 + 512]  + hg[jp2 + 512];
                float ag = sm.d.gacc[2][bi2][jl2] + eg[jp2 + 1024] + hg[jp2 + 1024];
                float ao = sm.d.gacc[3][bi2][jl2] + eg[jp2 + 1536] + hg[jp2 + 1536];
                float i_ = 1.f / (1.f + expf(-ai));
                float f_ = 1.f / (1.f + expf(-af));
                float o_ = 1.f / (1.f + expf(-ao));
                float gv = tanhf(ag);
                float c = f_ * g_c[b * HH + jp2] + i_ * gv;
                float h = o_ * tanhf(c);
                g_c[b * HH + jp2] = c;
                g_h[b * HH + jp2] = h;
                g_hze[(size_t)(b * TT + t) * HZE + jp2] = h;
            }
        }
        grid_sync();
    }
}

// ---------------- launch ----------------
extern "C" void kernel_launch(void* const* d_in, const int* in_sizes, int n_in,
                              void* d_out, int out_size) {
    const float* a      = (const float*)d_in[0];
    const float* h0     = (const float*)d_in[1];
    const float* c0     = (const float*)d_in[2];
    const int*   y      = (const int*)d_in[3];
    const float* att_w1 = (const float*)d_in[4];
    const float* att_b1 = (const float*)d_in[5];
    const float* att_w2 = (const float*)d_in[6];
    const float* att_b2 = (const float*)d_in[7];
    const float* att_w3 = (const float*)d_in[8];
    const float* att_b3 = (const float*)d_in[9];
    const float* w_ih   = (const float*)d_in[10];
    const float* w_hh   = (const float*)d_in[11];
    const float* b_ih   = (const float*)d_in[12];
    const float* b_hh   = (const float*)d_in[13];
    const float* embed  = (const float*)d_in[14];
    const float* out_w1 = (const float*)d_in[15];
    const float* out_b1 = (const float*)d_in[16];
    const float* out_w2 = (const float*)d_in[17];
    const float* out_b2 = (const float*)d_in[18];
    const float* out_w3 = (const float*)d_in[19];
    const float* out_b3 = (const float*)d_in[20];
    float* out = (float*)d_out;

    float *prea, *eseq, *egate, *hze, *x1, *x2;
    cudaGetSymbolAddress((void**)&prea,  g_prea);
    cudaGetSymbolAddress((void**)&eseq,  g_eseq);
    cudaGetSymbolAddress((void**)&egate, g_egate);
    cudaGetSymbolAddress((void**)&hze,   g_hze);
    cudaGetSymbolAddress((void**)&x1,    g_x1);
    cudaGetSymbolAddress((void**)&x2,    g_x2);

    k_embed<<<BB * TT, EE>>>(y, embed);

    k_sgemm<0><<<dim3((A1 + 63) / 64, (BB * LL + 63) / 64), 256>>>(
        a, DD, att_w1, A1, att_b1, prea, A1, BB * LL, A1, DD);
    k_sgemm<0><<<dim3((GG + 63) / 64, (BB * TT + 63) / 64), 256>>>(
        eseq, EE, w_ih + (size_t)DD * GG, GG, b_ih, egate, GG, BB * TT, GG, EE);

    k_steps<<<NBLK, NTHR>>>(a, h0, c0,
                            att_w1 + (size_t)DD * A1, w_hh, b_hh,
                            att_w2, att_b2, att_w3, att_b3, w_ih);

    k_sgemm<1><<<dim3((NH + 63) / 64, (BB * TT + 63) / 64), 256>>>(
        hze, HZE, out_w1, NH, out_b1, x1, NH, BB * TT, NH, HZE);
    k_sgemm<1><<<dim3((NH + 63) / 64, (BB * TT + 63) / 64), 256>>>(
        x1, NH, out_w2, NH, out_b2, x2, NH, BB * TT, NH, NH);
    k_sgemm<0><<<dim3((VV + 63) / 64, (BB * TT + 63) / 64), 256>>>(
        x2, NH, out_w3, VV, out_b3, out, VV, BB * TT, VV, NH);
}

// round 13
// speedup vs baseline: 1.2341x; 1.1909x over previous
#include <cuda_runtime.h>
#include <math.h>
#include <stdint.h>

#define BB 32
#define LL 196
#define DD 512
#define HH 512
#define EE 256
#define TT 128
#define VV 512
#define A1 256
#define A2 128
#define GG 2048            // 4*H
#define NH 358
#define HZE (HH + DD + EE) // 1280
#define NPG (A1 + GG)      // 2304
#define PADTOK 0
#define NBLK 296
#define NTHR 256
#define NGRP 37            // 296 / 8
#define XPA 260            // x1t (tf32) row stride: 256+4 -> conflict-free a-frag LDS

// ---------------- scratch (no allocation allowed) ----------------
__device__ float g_eseq[BB * TT * EE];
__device__ float g_prea[BB * LL * A1];
__device__ float g_egate[BB * TT * GG];
__device__ float g_h[BB * HH];
__device__ float g_c[BB * HH];
__device__ float g_hpg[BB * NPG];
__device__ float g_scores[BB * LL];
__device__ float g_z[BB * DD];
__device__ float g_hze[BB * TT * HZE];
__device__ float g_x1[BB * TT * NH];
__device__ float g_x2[BB * TT * NH];
__device__ uint32_t g_w2t[A1 * A2];   // w2 as tf32 bit patterns

// ---------------- hierarchical grid barrier (generation-tagged) ----------------
__device__ unsigned g_cnt0[NGRP];
__device__ unsigned g_cnt1;
__device__ volatile unsigned g_bar_gen;

__device__ __forceinline__ void grid_sync() {
    __syncthreads();
    if (threadIdx.x == 0) {
        unsigned gen = g_bar_gen;
        __threadfence();
        unsigned grp = (unsigned)blockIdx.x >> 3;
        unsigned old = atomicAdd(&g_cnt0[grp], 1u);
        bool done = false;
        if (old == 8u * gen + 7u) {
            unsigned o1 = atomicAdd(&g_cnt1, 1u);
            if (o1 == (unsigned)NGRP * gen + (NGRP - 1u)) {
                __threadfence();
                g_bar_gen = gen + 1u;
                done = true;
            }
        }
        if (!done) while (g_bar_gen == gen) {}
        __threadfence();
    }
    __syncthreads();
}

__device__ __forceinline__ float tanh_fast(float x) {
    float y;
    asm("tanh.approx.f32 %0, %1;" : "=f"(y) : "f"(x));
    return y;
}

__device__ __forceinline__ uint32_t f2tf32(float x) {
    uint32_t r;
    asm("cvt.rna.tf32.f32 %0, %1;" : "=r"(r) : "f"(x));
    return r;
}

__device__ __forceinline__ void mma_tf32(float c[4], uint32_t a0, uint32_t a1,
                                         uint32_t a2, uint32_t a3,
                                         uint32_t b0, uint32_t b1) {
    asm volatile(
        "mma.sync.aligned.m16n8k8.row.col.f32.tf32.tf32.f32 "
        "{%0,%1,%2,%3}, {%4,%5,%6,%7}, {%8,%9}, {%0,%1,%2,%3};"
        : "+f"(c[0]), "+f"(c[1]), "+f"(c[2]), "+f"(c[3])
        : "r"(a0), "r"(a1), "r"(a2), "r"(a3), "r"(b0), "r"(b1));
}

// ---------------- w2 -> tf32 conversion (once per launch) ----------------
__global__ void k_w2cvt(const float* __restrict__ w2) {
    int i = blockIdx.x * 256 + threadIdx.x;
    g_w2t[i] = f2tf32(w2[i]);
}

// ---------------- embedding gather (shift-right w/ pad) ----------------
__global__ void k_embed(const int* __restrict__ y, const float* __restrict__ embed) {
    int bt = blockIdx.x;
    int b = bt / TT, t = bt % TT;
    int tok = (t == 0) ? PADTOK : y[b * TT + (t - 1)];
    float v = embed[tok * EE + threadIdx.x];
    g_eseq[bt * EE + threadIdx.x] = v;
    g_hze[bt * HZE + HH + DD + threadIdx.x] = v;
}

// ---------------- generic tiled SGEMM: C = act(A*W + bias) ----------------
template <int ACT>
__global__ void k_sgemm(const float* __restrict__ A, int lda,
                        const float* __restrict__ W, int ldw,
                        const float* __restrict__ bias,
                        float* __restrict__ C, int ldc,
                        int M, int N, int K) {
    __shared__ float As[16][65];
    __shared__ float Ws[16][65];
    int tx = threadIdx.x % 16, ty = threadIdx.x / 16;
    int row0 = blockIdx.y * 64;
    int col0 = blockIdx.x * 64;
    float acc[4][4] = {};
    for (int k0 = 0; k0 < K; k0 += 16) {
        for (int i = threadIdx.x; i < 64 * 16; i += 256) {
            int r = i >> 4, kk = i & 15;
            int gr = row0 + r, gk = k0 + kk;
            As[kk][r] = (gr < M && gk < K) ? A[gr * lda + gk] : 0.f;
        }
        for (int i = threadIdx.x; i < 16 * 64; i += 256) {
            int kk = i >> 6, c = i & 63;
            int gk = k0 + kk, gc = col0 + c;
            Ws[kk][c] = (gk < K && gc < N) ? W[gk * ldw + gc] : 0.f;
        }
        __syncthreads();
#pragma unroll
        for (int kk = 0; kk < 16; kk++) {
            float a_[4], w_[4];
#pragma unroll
            for (int i = 0; i < 4; i++) a_[i] = As[kk][ty * 4 + i];
#pragma unroll
            for (int j = 0; j < 4; j++) w_[j] = Ws[kk][tx * 4 + j];
#pragma unroll
            for (int i = 0; i < 4; i++)
#pragma unroll
                for (int j = 0; j < 4; j++) acc[i][j] += a_[i] * w_[j];
        }
        __syncthreads();
    }
#pragma unroll
    for (int i = 0; i < 4; i++) {
        int r = row0 + ty * 4 + i;
        if (r >= M) continue;
#pragma unroll
        for (int j = 0; j < 4; j++) {
            int c = col0 + tx * 4 + j;
            if (c >= N) continue;
            float v = acc[i][j] + (bias ? bias[c] : 0.f);
            if (ACT == 1) v = tanhf(v);
            C[r * ldc + c] = v;
        }
    }
}

// ---------------- persistent step-loop kernel ----------------
struct SmemA1 { float h1[HH]; };
struct SmemA2 { float h4[4][HH]; };                                 // 8 KB
struct SmemBm { uint32_t x1t[32][XPA]; float red[32][4]; };         // ~33.8 KB
struct SmemC  { float al[LL]; float red[8]; float cpart[2][128]; };
struct SmemD  { float zs[4][DD]; float gacc[4][4][16]; };           // 9.2 KB
union StepSmem { SmemA1 a1; SmemA2 a2; SmemBm bm; SmemC c; SmemD d; };

__global__ __launch_bounds__(NTHR, 2)
void k_steps(const float* __restrict__ a_feat,
             const float* __restrict__ h0, const float* __restrict__ c0,
             const float* __restrict__ w1h,   // att_w1 + D*A1 (ld A1)
             const float* __restrict__ whh,   // ld GG
             const float* __restrict__ bhh,
             const float* __restrict__ b2,
             const float* __restrict__ w3, const float* __restrict__ b3,
             const float* __restrict__ wih) {
    __shared__ StepSmem sm;
    int bid = blockIdx.x;
    int tid = threadIdx.x;

    for (int i = bid * NTHR + tid; i < BB * HH; i += NBLK * NTHR) {
        g_h[i] = h0[i];
        g_c[i] = c0[i];
    }
    grid_sync();

    for (int t = 0; t < TT; t++) {
        // ======== P1: A1 (32 units) + A2 (256 units: 64 cols x 4 b) ========
        if (bid < 32) {
            int b = bid;
            for (int i = tid; i < HH; i += NTHR) sm.a1.h1[i] = g_h[b * HH + i];
            __syncthreads();
            float acc = 0.f;
#pragma unroll 16
            for (int k = 0; k < HH; k++)
                acc += sm.a1.h1[k] * __ldcg(&w1h[k * A1 + tid]);
            g_hpg[b * NPG + tid] = acc;
        } else if (bid < 288) {
            int a2u = bid - 32;
            int cch = a2u >> 3;               // 0..31 (64-col chunk)
            int bg = a2u & 7;                 // 0..7 (4 batches)
            for (int i = tid; i < 4 * HH; i += NTHR) {
                int bi = i >> 9, kk = i & 511;
                sm.a2.h4[bi][kk] = g_h[(bg * 4 + bi) * HH + kk];
            }
            __syncthreads();
            int col = cch * 64 + (tid & 63);  // 0..2047
            int bi = tid >> 6;                // 0..3
            const float* hrow = sm.a2.h4[bi];
            float acc = bhh[col];
#pragma unroll 32
            for (int k = 0; k < HH; k++)
                acc += hrow[k] * __ldcg(&whh[(size_t)k * GG + col]);
            g_hpg[(bg * 4 + bi) * NPG + A1 + col] = acc;
        }
        grid_sync();

        // ======== P2: attention via tf32 mma (224 units = 32 b x 7 l-tiles(32))
        if (bid < 224) {
            int b = bid / 7;
            int l0 = (bid % 7) * 32;
            // stage x1 tile as tf32: x1t[r][k], thread = column k, loops rows
            {
                float hpk = g_hpg[b * NPG + tid];     // k = tid (A1 == NTHR)
                const float* pr = g_prea + (size_t)(b * LL + l0) * A1 + tid;
#pragma unroll 8
                for (int r = 0; r < 32; r++) {
                    int l = l0 + r;
                    float v = 0.f;
                    if (l < LL) v = tanh_fast(__ldcg(&pr[(size_t)r * A1]) + hpk);
                    sm.bm.x1t[r][tid] = f2tf32(v);
                }
            }
            __syncthreads();
            int lane = tid & 31, w = tid >> 5;
            int wm = w & 1;                 // m16 tile (0/1)
            int wn = w >> 1;                // n32 block (0..3)
            int gid = lane >> 2, tig = lane & 3;
            int ra = wm * 16;
            float cfr[4][4] = {};           // [nt][reg]
#pragma unroll 4
            for (int ks = 0; ks < 32; ks++) {
                int k0 = ks * 8;
                uint32_t a0 = sm.bm.x1t[ra + gid][k0 + tig];
                uint32_t a1 = sm.bm.x1t[ra + gid + 8][k0 + tig];
                uint32_t a2r = sm.bm.x1t[ra + gid][k0 + tig + 4];
                uint32_t a3 = sm.bm.x1t[ra + gid + 8][k0 + tig + 4];
                const uint32_t* wb0 = &g_w2t[(k0 + tig) * A2 + wn * 32 + gid];
                const uint32_t* wb1 = &g_w2t[(k0 + tig + 4) * A2 + wn * 32 + gid];
#pragma unroll
                for (int nt = 0; nt < 4; nt++) {
                    uint32_t b0 = wb0[nt * 8];
                    uint32_t b1 = wb1[nt * 8];
                    mma_tf32(cfr[nt], a0, a1, a2r, a3, b0, b1);
                }
            }
            // epilogue: x2 = tanh(c + b2), p = x2*w3, reduce cols
            float p_lo = 0.f, p_hi = 0.f;   // rows ra+gid, ra+gid+8
#pragma unroll
            for (int nt = 0; nt < 4; nt++) {
                int cA = wn * 32 + nt * 8 + tig * 2;
                float b2a = b2[cA], b2b = b2[cA + 1];
                float w3a = w3[cA], w3b = w3[cA + 1];
                p_lo += tanh_fast(cfr[nt][0] + b2a) * w3a + tanh_fast(cfr[nt][1] + b2b) * w3b;
                p_hi += tanh_fast(cfr[nt][2] + b2a) * w3a + tanh_fast(cfr[nt][3] + b2b) * w3b;
            }
            p_lo += __shfl_down_sync(0xffffffffu, p_lo, 2, 4);
            p_lo += __shfl_down_sync(0xffffffffu, p_lo, 1, 4);
            p_hi += __shfl_down_sync(0xffffffffu, p_hi, 2, 4);
            p_hi += __shfl_down_sync(0xffffffffu, p_hi, 1, 4);
            if (tig == 0) {
                sm.bm.red[ra + gid][wn] = p_lo;
                sm.bm.red[ra + gid + 8][wn] = p_hi;
            }
            __syncthreads();
            if (tid < 32) {
                int l = l0 + tid;
                if (l < LL) {
                    float s = sm.bm.red[tid][0] + sm.bm.red[tid][1]
                            + sm.bm.red[tid][2] + sm.bm.red[tid][3] + b3[0];
                    g_scores[b * LL + l] = s;
                }
            }
        }
        grid_sync();

        // ======== P3: softmax + z (128 units = 32 b x 4 d-chunks(128)) ========
        if (bid < 128) {
            int b = bid >> 2;
            int dch = bid & 3;
            int lane = tid & 31, warp = tid >> 5;
            float v = (tid < LL) ? g_scores[b * LL + tid] : -1e30f;
            float m = v;
#pragma unroll
            for (int off = 16; off; off >>= 1) m = fmaxf(m, __shfl_xor_sync(0xffffffffu, m, off));
            if (lane == 0) sm.c.red[warp] = m;
            __syncthreads();
            m = sm.c.red[0];
#pragma unroll
            for (int i = 1; i < 8; i++) m = fmaxf(m, sm.c.red[i]);
            float e = (tid < LL) ? expf(v - m) : 0.f;
            __syncthreads();
            float sum = e;
#pragma unroll
            for (int off = 16; off; off >>= 1) sum += __shfl_xor_sync(0xffffffffu, sum, off);
            if (lane == 0) sm.c.red[warp] = sum;
            __syncthreads();
            sum = sm.c.red[0] + sm.c.red[1] + sm.c.red[2] + sm.c.red[3]
                + sm.c.red[4] + sm.c.red[5] + sm.c.red[6] + sm.c.red[7];
            float inv = 1.f / sum;
            if (tid < LL) sm.c.al[tid] = e * inv;
            __syncthreads();
            int dl = tid & 127;
            int lh = tid >> 7;
            int d = dch * 128 + dl;
            const float* ab = a_feat + (size_t)(b * LL + lh * 98) * DD + d;
            const float* alv = &sm.c.al[lh * 98];
            float acc = 0.f;
#pragma unroll 14
            for (int l = 0; l < 98; l++) acc += alv[l] * __ldcg(&ab[(size_t)l * DD]);
            sm.c.cpart[lh][dl] = acc;
            __syncthreads();
            if (tid < 128) {
                float zv = sm.c.cpart[0][tid] + sm.c.cpart[1][tid];
                int dg = dch * 128 + tid;
                g_z[b * DD + dg] = zv;
                g_hze[(size_t)(b * TT + t) * HZE + HH + dg] = zv;
            }
        }
        grid_sync();

        // ======== P4: LSTM (256 units = 32 jp-chunks(16) x 8 bg(4)) ===========
        if (bid < 256) {
            int jpch = bid >> 3;
            int bg = bid & 7;
            for (int i = tid; i < 4 * DD; i += NTHR) {
                int bi = i >> 9, kk = i & 511;
                sm.d.zs[bi][kk] = g_z[(bg * 4 + bi) * DD + kk];
            }
            __syncthreads();
            int jl = tid & 15;
            int gate = (tid >> 4) & 3;
            int bi = tid >> 6;
            int jp = jpch * 16 + jl;
            const float* Wg = wih + (size_t)gate * HH + jp;
            const float* zrow = sm.d.zs[bi];
            float acc = 0.f;
#pragma unroll 32
            for (int d = 0; d < DD; d++)
                acc += zrow[d] * __ldcg(&Wg[(size_t)d * GG]);
            sm.d.gacc[gate][bi][jl] = acc;
            __syncthreads();
            if (tid < 64) {
                int jl2 = tid & 15;
                int bi2 = tid >> 4;
                int b = bg * 4 + bi2;
                int jp2 = jpch * 16 + jl2;
                const float* eg = g_egate + (size_t)(b * TT + t) * GG;
                const float* hg = g_hpg + b * NPG + A1;
                float ai = sm.d.gacc[0][bi2][jl2] + eg[jp2]        + hg[jp2];
                float af = sm.d.gacc[1][bi2][jl2] + eg[jp2 + 512]  + hg[jp2 + 512];
                float ag = sm.d.gacc[2][bi2][jl2] + eg[jp2 + 1024] + hg[jp2 + 1024];
                float ao = sm.d.gacc[3][bi2][jl2] + eg[jp2 + 1536] + hg[jp2 + 1536];
                float i_ = 1.f / (1.f + expf(-ai));
                float f_ = 1.f / (1.f + expf(-af));
                float o_ = 1.f / (1.f + expf(-ao));
                float gv = tanhf(ag);
                float c = f_ * g_c[b * HH + jp2] + i_ * gv;
                float h = o_ * tanhf(c);
                g_c[b * HH + jp2] = c;
                g_h[b * HH + jp2] = h;
                g_hze[(size_t)(b * TT + t) * HZE + jp2] = h;
            }
        }
        grid_sync();
    }
}

// ---------------- launch ----------------
extern "C" void kernel_launch(void* const* d_in, const int* in_sizes, int n_in,
                              void* d_out, int out_size) {
    const float* a      = (const float*)d_in[0];
    const float* h0     = (const float*)d_in[1];
    const float* c0     = (const float*)d_in[2];
    const int*   y      = (const int*)d_in[3];
    const float* att_w1 = (const float*)d_in[4];
    const float* att_b1 = (const float*)d_in[5];
    const float* att_w2 = (const float*)d_in[6];
    const float* att_b2 = (const float*)d_in[7];
    const float* att_w3 = (const float*)d_in[8];
    const float* att_b3 = (const float*)d_in[9];
    const float* w_ih   = (const float*)d_in[10];
    const float* w_hh   = (const float*)d_in[11];
    const float* b_ih   = (const float*)d_in[12];
    const float* b_hh   = (const float*)d_in[13];
    const float* embed  = (const float*)d_in[14];
    const float* out_w1 = (const float*)d_in[15];
    const float* out_b1 = (const float*)d_in[16];
    const float* out_w2 = (const float*)d_in[17];
    const float* out_b2 = (const float*)d_in[18];
    const float* out_w3 = (const float*)d_in[19];
    const float* out_b3 = (const float*)d_in[20];
    float* out = (float*)d_out;

    float *prea, *eseq, *egate, *hze, *x1, *x2;
    cudaGetSymbolAddress((void**)&prea,  g_prea);
    cudaGetSymbolAddress((void**)&eseq,  g_eseq);
    cudaGetSymbolAddress((void**)&egate, g_egate);
    cudaGetSymbolAddress((void**)&hze,   g_hze);
    cudaGetSymbolAddress((void**)&x1,    g_x1);
    cudaGetSymbolAddress((void**)&x2,    g_x2);

    k_embed<<<BB * TT, EE>>>(y, embed);
    k_w2cvt<<<(A1 * A2) / 256, 256>>>(att_w2);

    k_sgemm<0><<<dim3((A1 + 63) / 64, (BB * LL + 63) / 64), 256>>>(
        a, DD, att_w1, A1, att_b1, prea, A1, BB * LL, A1, DD);
    k_sgemm<0><<<dim3((GG + 63) / 64, (BB * TT + 63) / 64), 256>>>(
        eseq, EE, w_ih + (size_t)DD * GG, GG, b_ih, egate, GG, BB * TT, GG, EE);

    k_steps<<<NBLK, NTHR>>>(a, h0, c0,
                            att_w1 + (size_t)DD * A1, w_hh, b_hh,
                            att_b2, att_w3, att_b3, w_ih);

    k_sgemm<1><<<dim3((NH + 63) / 64, (BB * TT + 63) / 64), 256>>>(
        hze, HZE, out_w1, NH, out_b1, x1, NH, BB * TT, NH, HZE);
    k_sgemm<1><<<dim3((NH + 63) / 64, (BB * TT + 63) / 64), 256>>>(
        x1, NH, out_w2, NH, out_b2, x2, NH, BB * TT, NH, NH);
    k_sgemm<0><<<dim3((VV + 63) / 64, (BB * TT + 63) / 64), 256>>>(
        x2, NH, out_w3, VV, out_b3, out, VV, BB * TT, VV, NH);
}